// round 1
// baseline (speedup 1.0000x reference)
#include <cuda_runtime.h>
#include <cstdint>

#define N_NODES 100000
#define N_EDGES 600000
#define FEAT    128
#define N_GRAPHS 100
#define BN_EPS  1e-5f

typedef unsigned long long ull;

// ---------------- scratch (device globals: no allocations allowed) ----------
__device__ float g_X[(size_t)N_NODES * FEAT];    // x = h*norm, later reused as Y (post-linear)
__device__ float g_AGG[(size_t)N_NODES * FEAT];  // scatter-sum accumulator
__device__ float g_sum[FEAT];
__device__ float g_sumsq[FEAT];
__device__ float g_scale[FEAT];
__device__ float g_shift[FEAT];

// ---------------- helpers ---------------------------------------------------
__device__ __forceinline__ ull pk(float x) {
    ull r; asm("mov.b64 %0, {%1, %1};" : "=l"(r) : "f"(x)); return r;
}
__device__ __forceinline__ void ffma2(ull& d, ull a, ull b) {
    asm("fma.rn.f32x2 %0, %1, %2, %3;" : "=l"(d) : "l"(a), "l"(b), "l"(d));
}
__device__ __forceinline__ float2 up(ull v) {
    float2 p; asm("mov.b64 {%0, %1}, %2;" : "=f"(p.x), "=f"(p.y) : "l"(v)); return p;
}

// ---------------- K0: x = h*norm, zero agg ----------------------------------
__global__ void k_scale_zero(const float* __restrict__ h, const float* __restrict__ norm) {
    int i = blockIdx.x * blockDim.x + threadIdx.x;   // float4 index, N_NODES*32 total
    float4 v = ((const float4*)h)[i];
    float nm = __ldg(&norm[i >> 5]);
    v.x *= nm; v.y *= nm; v.z *= nm; v.w *= nm;
    ((float4*)g_X)[i]   = v;
    ((float4*)g_AGG)[i] = make_float4(0.f, 0.f, 0.f, 0.f);
}

// ---------------- K0b: zero phis + stat accumulators ------------------------
__global__ void k_zero_small(float* __restrict__ phis) {
    int i = blockIdx.x * blockDim.x + threadIdx.x;   // 13056 total
    if (i < N_GRAPHS * FEAT)            phis[i] = 0.f;
    else if (i < N_GRAPHS * FEAT + FEAT)   g_sum[i - N_GRAPHS * FEAT] = 0.f;
    else                                   g_sumsq[i - N_GRAPHS * FEAT - FEAT] = 0.f;
}

// ---------------- K1: edge scatter-sum (one warp per edge) ------------------
__global__ void k_scatter(const int* __restrict__ src, const int* __restrict__ dst) {
    int e = blockIdx.x * (blockDim.x >> 5) + (threadIdx.x >> 5);
    if (e >= N_EDGES) return;
    int lane = threadIdx.x & 31;
    int s = __ldg(&src[e]);
    int d = __ldg(&dst[e]);
    float4 v = ((const float4*)(g_X + (size_t)s * FEAT))[lane];
    float* p = g_AGG + (size_t)d * FEAT + lane * 4;
    asm volatile("red.global.add.v4.f32 [%0], {%1, %2, %3, %4};"
                 :: "l"(p), "f"(v.x), "f"(v.y), "f"(v.z), "f"(v.w) : "memory");
}

// ---------------- K2: Y = relu((agg*norm) @ W + b), fused BN partial stats --
// Block: 256 threads (tx 0..15, ty 0..15), tile 128 rows x 128 cols, K=128 (full).
// Per thread: 8 rows (4 f32x2 row-pairs) x 8 cols = 32 packed accumulators.
#define AST 132   // smem strides (pad 4 -> 16B-aligned vectors, conflict-light)
__global__ void __launch_bounds__(256, 1)
k_gemm(const float* __restrict__ Wg, const float* __restrict__ bg,
       const float* __restrict__ norm) {
    extern __shared__ float sm[];
    float* As = sm;                 // [k][m] k-major, stride AST
    float* Ws = sm + 128 * AST;     // [k][c], stride AST
    int tid = threadIdx.x;
    int rowbase = blockIdx.x * 128;

    // fill A (transpose to k-major, multiply by norm)
    {
        int r = tid >> 1, half = tid & 1;
        int gr = rowbase + r;
        bool ok = (gr < N_NODES);
        float nm = ok ? __ldg(&norm[gr]) : 0.f;
        const float4* arow = (const float4*)(g_AGG + (size_t)gr * FEAT);
        #pragma unroll
        for (int j = 0; j < 16; j++) {
            int k = half * 64 + j * 4;
            float4 v = ok ? __ldg(&arow[k >> 2]) : make_float4(0.f, 0.f, 0.f, 0.f);
            As[(k + 0) * AST + r] = v.x * nm;
            As[(k + 1) * AST + r] = v.y * nm;
            As[(k + 2) * AST + r] = v.z * nm;
            As[(k + 3) * AST + r] = v.w * nm;
        }
    }
    // fill W (coalesced, no transpose)
    #pragma unroll
    for (int it = 0; it < 16; it++) {
        int g = tid + 256 * it;            // float4 index, 4096 total
        int k = g >> 5, c = (g & 31) * 4;
        *(float4*)&Ws[k * AST + c] = __ldg(&((const float4*)Wg)[g]);
    }
    __syncthreads();

    int tx = tid & 15, ty = tid >> 4;
    int m0 = ty * 8, c0 = tx * 8;

    ull acc[32];
    #pragma unroll
    for (int i = 0; i < 32; i++) acc[i] = 0ull;

    #pragma unroll 8
    for (int k = 0; k < 128; k++) {
        const float* ap = &As[k * AST + m0];
        ulonglong2 a01 = *(const ulonglong2*)ap;
        ulonglong2 a23 = *(const ulonglong2*)(ap + 4);
        const float* wp = &Ws[k * AST + c0];
        float4 w0 = *(const float4*)wp;
        float4 w1 = *(const float4*)(wp + 4);
        ull a2[4] = {a01.x, a01.y, a23.x, a23.y};
        ull wd[8] = {pk(w0.x), pk(w0.y), pk(w0.z), pk(w0.w),
                     pk(w1.x), pk(w1.y), pk(w1.z), pk(w1.w)};
        #pragma unroll
        for (int r2 = 0; r2 < 4; r2++)
            #pragma unroll
            for (int c = 0; c < 8; c++)
                ffma2(acc[r2 * 8 + c], a2[r2], wd[c]);
    }

    // epilogue: +bias, relu, store Y (into g_X), local column stats
    float bv[8];
    #pragma unroll
    for (int c = 0; c < 8; c++) bv[c] = __ldg(&bg[c0 + c]);
    float cs[8], cq[8];
    #pragma unroll
    for (int c = 0; c < 8; c++) { cs[c] = 0.f; cq[c] = 0.f; }

    #pragma unroll
    for (int r2 = 0; r2 < 4; r2++) {
        float2 pr[8];
        #pragma unroll
        for (int c = 0; c < 8; c++) pr[c] = up(acc[r2 * 8 + c]);
        #pragma unroll
        for (int half = 0; half < 2; half++) {
            int row = rowbase + m0 + 2 * r2 + half;
            float o[8];
            #pragma unroll
            for (int c = 0; c < 8; c++) {
                float v = (half ? pr[c].y : pr[c].x) + bv[c];
                o[c] = fmaxf(v, 0.f);
            }
            if (row < N_NODES) {
                float4 q0 = make_float4(o[0], o[1], o[2], o[3]);
                float4 q1 = make_float4(o[4], o[5], o[6], o[7]);
                *(float4*)&g_X[(size_t)row * FEAT + c0]     = q0;
                *(float4*)&g_X[(size_t)row * FEAT + c0 + 4] = q1;
                #pragma unroll
                for (int c = 0; c < 8; c++) { cs[c] += o[c]; cq[c] += o[c] * o[c]; }
            }
        }
    }

    // block-level column reduction for BN stats (reuse smem)
    __syncthreads();
    float* S1 = sm;               // [16][128]
    float* S2 = sm + 16 * 128;
    #pragma unroll
    for (int c = 0; c < 8; c++) {
        S1[ty * 128 + c0 + c] = cs[c];
        S2[ty * 128 + c0 + c] = cq[c];
    }
    __syncthreads();
    if (tid < 128) {
        float s = 0.f, q = 0.f;
        #pragma unroll
        for (int y = 0; y < 16; y++) { s += S1[y * 128 + tid]; q += S2[y * 128 + tid]; }
        atomicAdd(&g_sum[tid], s);
        atomicAdd(&g_sumsq[tid], q);
    }
}

// ---------------- K3: finalize BN affine ------------------------------------
__global__ void k_bnfin(const float* __restrict__ gamma, const float* __restrict__ beta) {
    int c = threadIdx.x;
    float mean = g_sum[c] * (1.f / N_NODES);
    float var  = g_sumsq[c] * (1.f / N_NODES) - mean * mean;
    float sc   = gamma[c] * rsqrtf(var + BN_EPS);
    g_scale[c] = sc;
    g_shift[c] = beta[c] - mean * sc;
}

// ---------------- K4: apply BN, write x_out, sorted segment-sum pooling -----
#define OUT_ROWS 256
__global__ void k_out(const int* __restrict__ gid,
                      float* __restrict__ xout, float* __restrict__ phis) {
    int c  = threadIdx.x;                 // 128 threads = one column each
    int r0 = blockIdx.x * OUT_ROWS;
    if (r0 >= N_NODES) return;
    int rend = min(r0 + OUT_ROWS, N_NODES);
    float sc = g_scale[c], sh = g_shift[c];
    float acc = 0.f;
    int gcur = __ldg(&gid[r0]);
    for (int r = r0; r < rend; r++) {
        int g = __ldg(&gid[r]);
        float v = g_X[(size_t)r * FEAT + c] * sc + sh;
        xout[(size_t)r * FEAT + c] = v;
        if (g != gcur) {
            atomicAdd(&phis[gcur * FEAT + c], acc);
            acc = 0.f; gcur = g;
        }
        acc += v;
    }
    atomicAdd(&phis[gcur * FEAT + c], acc);
}

// ---------------- launch -----------------------------------------------------
extern "C" void kernel_launch(void* const* d_in, const int* in_sizes, int n_in,
                              void* d_out, int out_size) {
    const float* h     = (const float*)d_in[0];
    const float* norm  = (const float*)d_in[1];
    const float* W     = (const float*)d_in[2];
    const float* b     = (const float*)d_in[3];
    const float* gamma = (const float*)d_in[4];
    const float* beta  = (const float*)d_in[5];
    const int*   src   = (const int*)d_in[6];
    const int*   dst   = (const int*)d_in[7];
    const int*   gid   = (const int*)d_in[8];
    float* xout = (float*)d_out;
    float* phis = xout + (size_t)N_NODES * FEAT;

    const int smem_gemm = 2 * 128 * AST * sizeof(float);   // 135168 B
    cudaFuncSetAttribute(k_gemm, cudaFuncAttributeMaxDynamicSharedMemorySize, smem_gemm);

    k_scale_zero<<<(N_NODES * 32) / 256, 256>>>(h, norm);
    k_zero_small<<<(N_GRAPHS * FEAT + 2 * FEAT + 255) / 256, 256>>>(phis);
    k_scatter<<<N_EDGES / 8, 256>>>(src, dst);
    k_gemm<<<(N_NODES + 127) / 128, 256, smem_gemm>>>(W, b, norm);
    k_bnfin<<<1, 128>>>(gamma, beta);
    k_out<<<(N_NODES + OUT_ROWS - 1) / OUT_ROWS, 128>>>(gid, xout, phis);
}